// round 11
// baseline (speedup 1.0000x reference)
#include <cuda_runtime.h>
#include <cstdint>

#define NN 16000
#define EE 256000
#define ET 272000   // EE + NN self loops
#define BB 32
#define IN_DIM 768
#define HID 256
#define H1 4
#define OUT_DIM 128
#define H2 2
#define D1 (H1*HID)    // 1024
#define D2 (H2*OUT_DIM) // 256
#define LN_EPS 1e-5f

// ---------------- scratch (static device globals; no allocation allowed) ----
__device__ float g_w1r[D1 * IN_DIM];         // tf32-rounded W1
__device__ float g_w2r[D2 * D1];             // tf32-rounded W2
__device__ float g_h1pre[(size_t)NN * D1];   // layer1 GEMM out
__device__ float g_h1[(size_t)NN * D1];      // layer1 output (elu, tf32-rounded)
__device__ float g_t2[(size_t)NN * D2];      // layer2 GEMM out
__device__ float g_as1[NN * H1];
__device__ float g_ad1[NN * H1];
__device__ float g_as2[NN * H2];
__device__ float g_ad2[NN * H2];
__device__ float g_m1[NN * H1];
__device__ float g_inv1[NN * H1];
__device__ float g_m2[NN * H2];
__device__ float g_inv2[NN * H2];
__device__ int   g_deg[NN];
__device__ int   g_rowptr[NN + 1];
__device__ int   g_fill[NN];
__device__ int   g_csrc[ET];
__device__ float g_pooled[BB * OUT_DIM];
__device__ int   g_cnt[BB];

__device__ __forceinline__ float lrelu(float x) { return x > 0.f ? x : 0.2f * x; }
__device__ __forceinline__ float elu(float x) { return x > 0.f ? x : expm1f(x); }

__device__ __forceinline__ float tf32r(float f) {
    uint32_t o;
    asm("cvt.rna.tf32.f32 %0, %1;" : "=r"(o) : "f"(f));
    return __uint_as_float(o);
}
__device__ __forceinline__ uint32_t tf32r_bits(uint32_t b) {
    uint32_t o;
    asm("cvt.rna.tf32.f32 %0, %1;" : "=r"(o) : "f"(__uint_as_float(b)));
    return o;
}

// ---------------- prep (GEMM branch): round W1/W2 + zero alpha/pool ---------
__global__ void prep_kernel(const float* __restrict__ W1,
                            const float* __restrict__ W2)
{
    int i = blockIdx.x * blockDim.x + threadIdx.x;
    const int n1 = D1 * IN_DIM / 4;
    const int n2 = D2 * D1 / 4;
    if (i < n1) {
        float4 v = ((const float4*)W1)[i];
        v.x = tf32r(v.x); v.y = tf32r(v.y); v.z = tf32r(v.z); v.w = tf32r(v.w);
        ((float4*)g_w1r)[i] = v;
    }
    if (i < n2) {
        float4 v = ((const float4*)W2)[i];
        v.x = tf32r(v.x); v.y = tf32r(v.y); v.z = tf32r(v.z); v.w = tf32r(v.w);
        ((float4*)g_w2r)[i] = v;
    }
    if (i < NN * H1) { g_as1[i] = 0.f; g_ad1[i] = 0.f; }
    if (i < NN * H2) { g_as2[i] = 0.f; g_ad2[i] = 0.f; }
    if (i < BB * OUT_DIM) g_pooled[i] = 0.f;
    if (i < BB) g_cnt[i] = 0;
}

// ---------------- CSR branch (second stream) --------------------------------
__global__ void zero_csr_kernel() {
    int i = blockIdx.x * blockDim.x + threadIdx.x;
    if (i < NN) { g_deg[i] = 0; g_fill[i] = 0; }
}

__global__ void hist_kernel(const int* __restrict__ ei) {
    int e = blockIdx.x * blockDim.x + threadIdx.x;
    if (e >= ET) return;
    int dst = (e < EE) ? ei[EE + e] : (e - EE);
    atomicAdd(&g_deg[dst], 1);
}

__global__ void scan_kernel() {
    __shared__ int warp_sums[32];
    __shared__ int carry_s;
    int t = threadIdx.x, lane = t & 31, w = t >> 5;
    if (t == 0) { carry_s = 0; g_rowptr[0] = 0; }
    __syncthreads();
    for (int base = 0; base < NN; base += 1024) {
        int i = base + t;
        int x = (i < NN) ? g_deg[i] : 0;
#pragma unroll
        for (int o = 1; o < 32; o <<= 1) {
            int y = __shfl_up_sync(0xffffffffu, x, o);
            if (lane >= o) x += y;
        }
        if (lane == 31) warp_sums[w] = x;
        __syncthreads();
        if (w == 0) {
            int s = warp_sums[lane];
#pragma unroll
            for (int o = 1; o < 32; o <<= 1) {
                int y = __shfl_up_sync(0xffffffffu, s, o);
                if (lane >= o) s += y;
            }
            warp_sums[lane] = s;
        }
        __syncthreads();
        int pre = (w > 0 ? warp_sums[w - 1] : 0) + carry_s;
        if (i < NN) g_rowptr[i + 1] = x + pre;
        __syncthreads();
        if (t == 0) carry_s += warp_sums[31];
        __syncthreads();
    }
}

__global__ void scatter_kernel(const int* __restrict__ ei) {
    int e = blockIdx.x * blockDim.x + threadIdx.x;
    if (e >= ET) return;
    int src, dst;
    if (e < EE) { src = ei[e]; dst = ei[EE + e]; }
    else        { src = dst = e - EE; }
    int pos = g_rowptr[dst] + atomicAdd(&g_fill[dst], 1);
    g_csrc[pos] = src;
}

// ---------------- TF32 tensor-core GEMM (cp.async + ldmatrix) ---------------
// A may be raw fp32: fragments are cvt.rna'd to tf32 after ldmatrix.
// B must be pre-rounded to tf32.
#define TBM 128
#define TBN 128
#define TBK 16
#define A_BYTES (TBM * 64)
#define B_BYTES (TBN * 64)
#define STAGE_BYTES (A_BYTES + B_BYTES)   // 16384
#define NSTAGE 4
#define SMEM_BYTES (NSTAGE * STAGE_BYTES) // 65536

__device__ __forceinline__ int sw_of(int r) { return (r ^ (r >> 2)) & 3; }

__global__ __launch_bounds__(256, 2) void sgemm_tf32(
    const float* __restrict__ A, const float* __restrict__ B,
    float* __restrict__ C, int M, int N, int K,
    const float* __restrict__ av_src, const float* __restrict__ av_dst,
    float* __restrict__ out_as, float* __restrict__ out_ad,
    int head_bits, int nheads)
{
    extern __shared__ uint32_t smem[];
    const uint32_t smem_base = (uint32_t)__cvta_generic_to_shared(smem);

    const int tid  = threadIdx.x;
    const int lane = tid & 31;
    const int wid  = tid >> 5;
    const int g    = lane >> 2;
    const int tig  = lane & 3;
    const int wm   = wid >> 2;
    const int wn   = wid & 3;
    const int bm   = blockIdx.y * TBM;
    const int bn   = blockIdx.x * TBN;

    // A ldmatrix lane roles (x4: 16 rows x 2 chunks)
    const int rlA = (lane & 7) + ((lane >> 3) & 1) * 8;
    const int caA = lane >> 4;

    uint32_t aoff[4]; int aswz[4];
#pragma unroll
    for (int mt = 0; mt < 4; mt++) {
        int r = wm * 64 + mt * 16 + rlA;
        aoff[mt] = (uint32_t)(r * 64);
        aswz[mt] = sw_of(r);
    }

    // B ldmatrix x4 lane roles: group q=lane>>3 -> (nt pair member, k chunk)
    const int q  = lane >> 3;       // 0..3
    const int cq = q & 1;           // chunk select within kstep
    uint32_t boff2[2]; int bswz2[2];
#pragma unroll
    for (int p = 0; p < 2; p++) {
        int ntp = 2 * p + (q >> 1);
        int r = wn * 32 + ntp * 8 + (lane & 7);
        boff2[p] = (uint32_t)(A_BYTES + r * 64);
        bswz2[p] = sw_of(r);
    }

    float acc[4][4][4];
#pragma unroll
    for (int mt = 0; mt < 4; mt++)
#pragma unroll
        for (int nt = 0; nt < 4; nt++)
#pragma unroll
            for (int i = 0; i < 4; i++) acc[mt][nt][i] = 0.f;

    const int KT = K / TBK;

    auto load_stage = [&](int s, int kt) {
        const uint32_t base = smem_base + s * STAGE_BYTES;
        const int k0 = kt * TBK;
        {
            int m = tid >> 2, kc = tid & 3;
            uint32_t dst = base + (uint32_t)(m * 64 + ((kc ^ sw_of(m)) << 4));
            const float* src = A + (size_t)(bm + m) * K + k0 + kc * 4;
            asm volatile("cp.async.cg.shared.global [%0], [%1], 16;" :: "r"(dst), "l"(src));
            int c2 = tid + 256;
            int m2 = c2 >> 2, kc2 = c2 & 3;
            uint32_t dst2 = base + (uint32_t)(m2 * 64 + ((kc2 ^ sw_of(m2)) << 4));
            const float* src2 = A + (size_t)(bm + m2) * K + k0 + kc2 * 4;
            asm volatile("cp.async.cg.shared.global [%0], [%1], 16;" :: "r"(dst2), "l"(src2));
        }
        {
            int n = tid >> 2, kc = tid & 3;
            uint32_t dst = base + A_BYTES + (uint32_t)(n * 64 + ((kc ^ sw_of(n)) << 4));
            const float* src = B + (size_t)(bn + n) * K + k0 + kc * 4;
            asm volatile("cp.async.cg.shared.global [%0], [%1], 16;" :: "r"(dst), "l"(src));
            int c2 = tid + 256;
            int n2 = c2 >> 2, kc2 = c2 & 3;
            uint32_t dst2 = base + A_BYTES + (uint32_t)(n2 * 64 + ((kc2 ^ sw_of(n2)) << 4));
            const float* src2 = B + (size_t)(bn + n2) * K + k0 + kc2 * 4;
            asm volatile("cp.async.cg.shared.global [%0], [%1], 16;" :: "r"(dst2), "l"(src2));
        }
    };

#pragma unroll
    for (int s = 0; s < NSTAGE - 1; s++) {
        load_stage(s, s);
        asm volatile("cp.async.commit_group;");
    }

    for (int kt = 0; kt < KT; kt++) {
        const int s = kt & (NSTAGE - 1);
        asm volatile("cp.async.wait_group %0;" :: "n"(NSTAGE - 2));
        __syncthreads();

        const uint32_t base = smem_base + s * STAGE_BYTES;

#pragma unroll
        for (int ks = 0; ks < 2; ks++) {
            const int j0 = ks * 2;
            uint32_t af[4][4];
#pragma unroll
            for (int mt = 0; mt < 4; mt++) {
                uint32_t addr = base + aoff[mt] + (uint32_t)((((j0 + caA) ^ aswz[mt])) << 4);
                asm volatile("ldmatrix.sync.aligned.m8n8.x4.shared.b16 {%0,%1,%2,%3}, [%4];"
                    : "=r"(af[mt][0]), "=r"(af[mt][1]), "=r"(af[mt][2]), "=r"(af[mt][3])
                    : "r"(addr));
            }
            // round A fragments to tf32 (rna) — keeps reference-matching rounding
#pragma unroll
            for (int mt = 0; mt < 4; mt++)
#pragma unroll
                for (int i = 0; i < 4; i++)
                    af[mt][i] = tf32r_bits(af[mt][i]);

            uint32_t bf[4][2];
#pragma unroll
            for (int p = 0; p < 2; p++) {
                uint32_t addr = base + boff2[p] + (uint32_t)((((j0 + cq) ^ bswz2[p])) << 4);
                asm volatile("ldmatrix.sync.aligned.m8n8.x4.shared.b16 {%0,%1,%2,%3}, [%4];"
                    : "=r"(bf[2 * p][0]), "=r"(bf[2 * p][1]),
                      "=r"(bf[2 * p + 1][0]), "=r"(bf[2 * p + 1][1])
                    : "r"(addr));
            }
#pragma unroll
            for (int mt = 0; mt < 4; mt++)
#pragma unroll
                for (int nt = 0; nt < 4; nt++) {
                    asm volatile(
                        "mma.sync.aligned.m16n8k8.row.col.f32.tf32.tf32.f32 "
                        "{%0,%1,%2,%3}, {%4,%5,%6,%7}, {%8,%9}, {%0,%1,%2,%3};"
                        : "+f"(acc[mt][nt][0]), "+f"(acc[mt][nt][1]),
                          "+f"(acc[mt][nt][2]), "+f"(acc[mt][nt][3])
                        : "r"(af[mt][0]), "r"(af[mt][1]), "r"(af[mt][2]), "r"(af[mt][3]),
                          "r"(bf[nt][0]), "r"(bf[nt][1]));
                }
        }

        if (kt + NSTAGE - 1 < KT) load_stage((kt + NSTAGE - 1) & (NSTAGE - 1), kt + NSTAGE - 1);
        asm volatile("cp.async.commit_group;");
    }

    // epilogue: store C
#pragma unroll
    for (int mt = 0; mt < 4; mt++) {
        int r0 = bm + wm * 64 + mt * 16 + g;
#pragma unroll
        for (int nt = 0; nt < 4; nt++) {
            int cc = bn + wn * 32 + nt * 8 + tig * 2;
            *(float2*)(C + (size_t)r0 * N + cc) = make_float2(acc[mt][nt][0], acc[mt][nt][1]);
            *(float2*)(C + (size_t)(r0 + 8) * N + cc) = make_float2(acc[mt][nt][2], acc[mt][nt][3]);
        }
    }

    // fused alpha epilogue
    if (av_src) {
        const int head = bn >> head_bits;
        const int omask = (1 << head_bits) - 1;
        const int obase = head << head_bits;
        float asv[4][2], adv[4][2];
#pragma unroll
        for (int nt = 0; nt < 4; nt++) {
#pragma unroll
            for (int i = 0; i < 2; i++) {
                int c = bn + wn * 32 + nt * 8 + tig * 2 + i;
                int o = c & omask;
                asv[nt][i] = av_src[obase + o];
                adv[nt][i] = av_dst[obase + o];
            }
        }
#pragma unroll
        for (int mt = 0; mt < 4; mt++) {
            float s0 = 0.f, s1 = 0.f, d0 = 0.f, d1 = 0.f;
#pragma unroll
            for (int nt = 0; nt < 4; nt++) {
                s0 += acc[mt][nt][0] * asv[nt][0] + acc[mt][nt][1] * asv[nt][1];
                d0 += acc[mt][nt][0] * adv[nt][0] + acc[mt][nt][1] * adv[nt][1];
                s1 += acc[mt][nt][2] * asv[nt][0] + acc[mt][nt][3] * asv[nt][1];
                d1 += acc[mt][nt][2] * adv[nt][0] + acc[mt][nt][3] * adv[nt][1];
            }
#pragma unroll
            for (int o = 1; o < 4; o <<= 1) {
                s0 += __shfl_xor_sync(0xffffffffu, s0, o);
                s1 += __shfl_xor_sync(0xffffffffu, s1, o);
                d0 += __shfl_xor_sync(0xffffffffu, d0, o);
                d1 += __shfl_xor_sync(0xffffffffu, d1, o);
            }
            if (tig == 0) {
                int r0 = bm + wm * 64 + mt * 16 + g;
                atomicAdd(&out_as[r0 * nheads + head], s0);
                atomicAdd(&out_ad[r0 * nheads + head], d0);
                atomicAdd(&out_as[(r0 + 8) * nheads + head], s1);
                atomicAdd(&out_ad[(r0 + 8) * nheads + head], d1);
            }
        }
    }
}

// ---------------- softmax stats: warp per node, shfl-only -------------------
__global__ __launch_bounds__(256) void stats1_kernel() {
    int n = (blockIdx.x * 256 + threadIdx.x) >> 5;
    int lane = threadIdx.x & 31;
    if (n >= NN) return;
    int row = g_rowptr[n], deg = g_rowptr[n + 1] - row;
    float4 adv = *(const float4*)(g_ad1 + n * 4);
    float m0 = -1e30f, m1 = -1e30f, m2 = -1e30f, m3 = -1e30f;
    for (int j = lane; j < deg; j += 32) {
        int s = g_csrc[row + j];
        float4 a = *(const float4*)(g_as1 + s * 4);
        m0 = fmaxf(m0, lrelu(a.x + adv.x));
        m1 = fmaxf(m1, lrelu(a.y + adv.y));
        m2 = fmaxf(m2, lrelu(a.z + adv.z));
        m3 = fmaxf(m3, lrelu(a.w + adv.w));
    }
#pragma unroll
    for (int o = 16; o; o >>= 1) {
        m0 = fmaxf(m0, __shfl_xor_sync(0xffffffffu, m0, o));
        m1 = fmaxf(m1, __shfl_xor_sync(0xffffffffu, m1, o));
        m2 = fmaxf(m2, __shfl_xor_sync(0xffffffffu, m2, o));
        m3 = fmaxf(m3, __shfl_xor_sync(0xffffffffu, m3, o));
    }
    float d0 = 0.f, d1 = 0.f, d2 = 0.f, d3 = 0.f;
    for (int j = lane; j < deg; j += 32) {
        int s = g_csrc[row + j];
        float4 a = *(const float4*)(g_as1 + s * 4);
        d0 += __expf(lrelu(a.x + adv.x) - m0);
        d1 += __expf(lrelu(a.y + adv.y) - m1);
        d2 += __expf(lrelu(a.z + adv.z) - m2);
        d3 += __expf(lrelu(a.w + adv.w) - m3);
    }
#pragma unroll
    for (int o = 16; o; o >>= 1) {
        d0 += __shfl_xor_sync(0xffffffffu, d0, o);
        d1 += __shfl_xor_sync(0xffffffffu, d1, o);
        d2 += __shfl_xor_sync(0xffffffffu, d2, o);
        d3 += __shfl_xor_sync(0xffffffffu, d3, o);
    }
    if (lane == 0) {
        *(float4*)(g_m1 + n * 4) = make_float4(m0, m1, m2, m3);
        *(float4*)(g_inv1 + n * 4) = make_float4(
            1.f / (d0 + 1e-16f), 1.f / (d1 + 1e-16f),
            1.f / (d2 + 1e-16f), 1.f / (d3 + 1e-16f));
    }
}

__global__ __launch_bounds__(256) void stats2_kernel() {
    int n = (blockIdx.x * 256 + threadIdx.x) >> 5;
    int lane = threadIdx.x & 31;
    if (n >= NN) return;
    int row = g_rowptr[n], deg = g_rowptr[n + 1] - row;
    float2 adv = *(const float2*)(g_ad2 + n * 2);
    float m0 = -1e30f, m1 = -1e30f;
    for (int j = lane; j < deg; j += 32) {
        int s = g_csrc[row + j];
        float2 a = *(const float2*)(g_as2 + s * 2);
        m0 = fmaxf(m0, lrelu(a.x + adv.x));
        m1 = fmaxf(m1, lrelu(a.y + adv.y));
    }
#pragma unroll
    for (int o = 16; o; o >>= 1) {
        m0 = fmaxf(m0, __shfl_xor_sync(0xffffffffu, m0, o));
        m1 = fmaxf(m1, __shfl_xor_sync(0xffffffffu, m1, o));
    }
    float d0 = 0.f, d1 = 0.f;
    for (int j = lane; j < deg; j += 32) {
        int s = g_csrc[row + j];
        float2 a = *(const float2*)(g_as2 + s * 2);
        d0 += __expf(lrelu(a.x + adv.x) - m0);
        d1 += __expf(lrelu(a.y + adv.y) - m1);
    }
#pragma unroll
    for (int o = 16; o; o >>= 1) {
        d0 += __shfl_xor_sync(0xffffffffu, d0, o);
        d1 += __shfl_xor_sync(0xffffffffu, d1, o);
    }
    if (lane == 0) {
        *(float2*)(g_m2 + n * 2) = make_float2(m0, m1);
        *(float2*)(g_inv2 + n * 2) = make_float2(1.f / (d0 + 1e-16f), 1.f / (d1 + 1e-16f));
    }
}

// ---------------- layer1 aggregation (block per node, no reductions) --------
#define CH1 512
__global__ __launch_bounds__(256) void gat1_agg(
    const float* __restrict__ h, const float* __restrict__ b1,
    float* __restrict__ out)
{
    __shared__ float s_ex[CH1 * 4];
    __shared__ int   s_src[CH1];
    int n = blockIdx.x, tid = threadIdx.x;
    int row = g_rowptr[n];
    int deg = g_rowptr[n + 1] - row;
    float4 adv = *(const float4*)(g_ad1 + n * 4);
    float4 m   = *(const float4*)(g_m1 + n * 4);
    float4 inv = *(const float4*)(g_inv1 + n * 4);

    const int head = tid >> 6;          // 0..3
    const int off  = (tid & 63) << 2;   // 0..252

    float4 acc = make_float4(0.f, 0.f, 0.f, 0.f);
    const float* hb = h + head * 256 + off;
    for (int base = 0; base < deg; base += CH1) {
        int cnt = min(CH1, deg - base);
        for (int j = tid; j < cnt; j += 256) {
            int s = g_csrc[row + base + j];
            s_src[j] = s;
            float4 a = *(const float4*)(g_as1 + s * 4);
            s_ex[j * 4 + 0] = __expf(lrelu(a.x + adv.x) - m.x) * inv.x;
            s_ex[j * 4 + 1] = __expf(lrelu(a.y + adv.y) - m.y) * inv.y;
            s_ex[j * 4 + 2] = __expf(lrelu(a.z + adv.z) - m.z) * inv.z;
            s_ex[j * 4 + 3] = __expf(lrelu(a.w + adv.w) - m.w) * inv.w;
        }
        __syncthreads();
#pragma unroll 4
        for (int j = 0; j < cnt; j++) {
            int s = s_src[j];
            float w = s_ex[j * 4 + head];
            float4 v = *(const float4*)(hb + (size_t)s * D1);
            acc.x = fmaf(v.x, w, acc.x);
            acc.y = fmaf(v.y, w, acc.y);
            acc.z = fmaf(v.z, w, acc.z);
            acc.w = fmaf(v.w, w, acc.w);
        }
        __syncthreads();
    }

    float4 bv = *(const float4*)(b1 + head * 256 + off);
    float4 o4;
    o4.x = tf32r(elu(acc.x + bv.x));
    o4.y = tf32r(elu(acc.y + bv.y));
    o4.z = tf32r(elu(acc.z + bv.z));
    o4.w = tf32r(elu(acc.w + bv.w));
    *(float4*)(out + (size_t)n * D1 + head * 256 + off) = o4;
}

// ---------------- layer2 aggregation (block per node, no reductions) --------
#define CH2 512
__global__ __launch_bounds__(128) void gat2_agg(
    const float* __restrict__ h, const float* __restrict__ b2,
    float* __restrict__ h2out)
{
    __shared__ float s_ex[CH2 * 2];
    __shared__ int   s_src[CH2];
    __shared__ float s_comb[128];
    int n = blockIdx.x, tid = threadIdx.x;
    int row = g_rowptr[n];
    int deg = g_rowptr[n + 1] - row;
    float2 adv = *(const float2*)(g_ad2 + n * 2);
    float2 m   = *(const float2*)(g_m2 + n * 2);
    float2 inv = *(const float2*)(g_inv2 + n * 2);

    const int head = tid >> 6;          // 0..1
    const int foff = (tid & 63) << 1;   // 0..126

    float2 acc = make_float2(0.f, 0.f);
    const float* hb = h + head * OUT_DIM + foff;
    for (int base = 0; base < deg; base += CH2) {
        int cnt = min(CH2, deg - base);
        for (int j = tid; j < cnt; j += 128) {
            int s = g_csrc[row + base + j];
            s_src[j] = s;
            float2 a = *(const float2*)(g_as2 + s * 2);
            s_ex[j * 2 + 0] = __expf(lrelu(a.x + adv.x) - m.x) * inv.x;
            s_ex[j * 2 + 1] = __expf(lrelu(a.y + adv.y) - m.y) * inv.y;
        }
        __syncthreads();
#pragma unroll 4
        for (int j = 0; j < cnt; j++) {
            int s = s_src[j];
            float w = s_ex[j * 2 + head];
            float2 v = *(const float2*)(hb + (size_t)s * D2);
            acc.x = fmaf(v.x, w, acc.x);
            acc.y = fmaf(v.y, w, acc.y);
        }
        __syncthreads();
    }

    if (head == 1) { s_comb[foff] = acc.x; s_comb[foff + 1] = acc.y; }
    __syncthreads();
    if (head == 0) {
        float ox = (acc.x + s_comb[foff]) * 0.5f + b2[foff];
        float oy = (acc.y + s_comb[foff + 1]) * 0.5f + b2[foff + 1];
        *(float2*)(h2out + (size_t)n * OUT_DIM + foff) = make_float2(elu(ox), elu(oy));
    }
}

// ---------------- pooling (run-length on sorted batch, 125 blocks) ----------
__global__ __launch_bounds__(128) void pool_kernel(
    const float* __restrict__ h2, const int* __restrict__ batch)
{
    __shared__ int s_b[128];
    int blk = blockIdx.x, f = threadIdx.x;
    int n0 = blk * 128;
    s_b[f] = batch[n0 + f];
    __syncthreads();

    float acc = 0.f;
    int cur = s_b[0];
    int cnt = 0;
#pragma unroll 4
    for (int j = 0; j < 128; j++) {
        int b = s_b[j];
        if (b != cur) {
            atomicAdd(&g_pooled[cur * OUT_DIM + f], acc);
            if (f == 0) atomicAdd(&g_cnt[cur], cnt);
            acc = 0.f; cnt = 0; cur = b;
        }
        acc += h2[(size_t)(n0 + j) * OUT_DIM + f];
        cnt++;
    }
    atomicAdd(&g_pooled[cur * OUT_DIM + f], acc);
    if (f == 0) atomicAdd(&g_cnt[cur], cnt);
}

// ---------------- proj + layernorm (block per graph, 768 threads) -----------
__global__ __launch_bounds__(768) void proj_ln_kernel(
    const float* __restrict__ W, const float* __restrict__ pb,
    const float* __restrict__ g, const float* __restrict__ beta,
    float* __restrict__ out)
{
    __shared__ float sp[OUT_DIM];
    __shared__ float red[768];
    int b = blockIdx.x, j = threadIdx.x;
    float c = (float)max(g_cnt[b], 1);
    if (j < OUT_DIM) sp[j] = g_pooled[b * OUT_DIM + j] / c;
    __syncthreads();
    float z = pb[j];
    const float* w = W + (size_t)j * OUT_DIM;
#pragma unroll 8
    for (int k = 0; k < OUT_DIM; k++) z = fmaf(sp[k], w[k], z);

    red[j] = z; __syncthreads();
    if (j < 256) red[j] += red[j + 512];
    __syncthreads();
    if (j < 256) red[j] += red[j + 256];
    __syncthreads();
    for (int off = 128; off; off >>= 1) { if (j < off) red[j] += red[j + off]; __syncthreads(); }
    float mean = red[0] / 768.f;
    __syncthreads();
    float dz = z - mean;
    red[j] = dz * dz; __syncthreads();
    if (j < 256) red[j] += red[j + 512];
    __syncthreads();
    if (j < 256) red[j] += red[j + 256];
    __syncthreads();
    for (int off = 128; off; off >>= 1) { if (j < off) red[j] += red[j + off]; __syncthreads(); }
    float var = red[0] / 768.f;
    out[(size_t)b * 768 + j] = dz * rsqrtf(var + LN_EPS) * g[j] + beta[j];
}

// ---------------- launch ----------------------------------------------------
extern "C" void kernel_launch(void* const* d_in, const int* in_sizes, int n_in,
                              void* d_out, int out_size)
{
    const float* x   = (const float*)d_in[0];
    const int*   ei  = (const int*)  d_in[1];
    const int*   bat = (const int*)  d_in[2];
    const float* W1  = (const float*)d_in[3];
    const float* a1s = (const float*)d_in[4];
    const float* a1d = (const float*)d_in[5];
    const float* b1  = (const float*)d_in[6];
    const float* W2  = (const float*)d_in[7];
    const float* a2s = (const float*)d_in[8];
    const float* a2d = (const float*)d_in[9];
    const float* b2  = (const float*)d_in[10];
    const float* pW  = (const float*)d_in[11];
    const float* pb  = (const float*)d_in[12];
    const float* lg  = (const float*)d_in[13];
    const float* lb  = (const float*)d_in[14];

    float* out = (float*)d_out;
    float* ge  = out;                 // (32, 768)
    float* h2  = out + BB * 768;      // (16000, 128)

    float *w1r, *w2r, *h1pre, *h1, *t2, *as1, *ad1, *as2, *ad2;
    cudaGetSymbolAddress((void**)&w1r, g_w1r);
    cudaGetSymbolAddress((void**)&w2r, g_w2r);
    cudaGetSymbolAddress((void**)&h1pre, g_h1pre);
    cudaGetSymbolAddress((void**)&h1, g_h1);
    cudaGetSymbolAddress((void**)&t2, g_t2);
    cudaGetSymbolAddress((void**)&as1, g_as1);
    cudaGetSymbolAddress((void**)&ad1, g_ad1);
    cudaGetSymbolAddress((void**)&as2, g_as2);
    cudaGetSymbolAddress((void**)&ad2, g_ad2);

    cudaFuncSetAttribute(sgemm_tf32, cudaFuncAttributeMaxDynamicSharedMemorySize,
                         SMEM_BYTES);

    // fork a second stream for the CSR build (independent of prep/GEMM1)
    cudaStream_t s2;
    cudaStreamCreateWithFlags(&s2, cudaStreamNonBlocking);
    cudaEvent_t ev_fork, ev_join;
    cudaEventCreateWithFlags(&ev_fork, cudaEventDisableTiming);
    cudaEventCreateWithFlags(&ev_join, cudaEventDisableTiming);

    cudaEventRecord(ev_fork, 0);
    cudaStreamWaitEvent(s2, ev_fork, 0);

    // slots: 1 prep, 2 zero_csr, 3 hist, 4 GEMM1 (ncu capture slot)
    prep_kernel<<<(D1 * IN_DIM / 4 + 255) / 256, 256>>>(W1, W2);             // 1 (s0)
    zero_csr_kernel<<<(NN + 255) / 256, 256, 0, s2>>>();                     // 2 (s2)
    hist_kernel<<<(ET + 255) / 256, 256, 0, s2>>>(ei);                       // 3 (s2)
    {
        dim3 grid(D1 / TBN, NN / TBM);   // (8, 125)                         // 4 (s0)
        sgemm_tf32<<<grid, 256, SMEM_BYTES>>>(x, w1r, h1pre, NN, D1, IN_DIM,
                                              a1s, a1d, as1, ad1, 8, H1);
    }
    scan_kernel<<<1, 1024, 0, s2>>>();                                       // 5 (s2)
    scatter_kernel<<<(ET + 255) / 256, 256, 0, s2>>>(ei);                    // 6 (s2)
    cudaEventRecord(ev_join, s2);
    cudaStreamWaitEvent(0, ev_join, 0);

    stats1_kernel<<<(NN * 32 + 255) / 256, 256>>>();                         // 7
    gat1_agg<<<NN, 256>>>(h1pre, b1, h1);                                    // 8
    {
        dim3 grid(D2 / TBN, NN / TBM);   // (2, 125)                         // 9
        sgemm_tf32<<<grid, 256, SMEM_BYTES>>>(h1, w2r, t2, NN, D2, D1,
                                              a2s, a2d, as2, ad2, 7, H2);
    }
    stats2_kernel<<<(NN * 32 + 255) / 256, 256>>>();                         // 10
    gat2_agg<<<NN, 128>>>(t2, b2, h2);                                       // 11
    pool_kernel<<<NN / 128, 128>>>(h2, bat);                                 // 12
    proj_ln_kernel<<<BB, 768>>>(pW, pb, lg, lb, ge);                         // 13

    cudaEventDestroy(ev_fork);
    cudaEventDestroy(ev_join);
    cudaStreamDestroy(s2);
}

// round 13
// speedup vs baseline: 1.0043x; 1.0043x over previous
#include <cuda_runtime.h>
#include <cstdint>

#define NN 16000
#define EE 256000
#define ET 272000   // EE + NN self loops
#define BB 32
#define IN_DIM 768
#define HID 256
#define H1 4
#define OUT_DIM 128
#define H2 2
#define D1 (H1*HID)    // 1024
#define D2 (H2*OUT_DIM) // 256
#define LN_EPS 1e-5f

// ---------------- scratch (static device globals; no allocation allowed) ----
__device__ float g_xr[(size_t)NN * IN_DIM];  // tf32-rounded x
__device__ float g_w1r[D1 * IN_DIM];         // tf32-rounded W1
__device__ float g_w2r[D2 * D1];             // tf32-rounded W2
__device__ float g_h1pre[(size_t)NN * D1];   // layer1 GEMM out
__device__ float g_h1[(size_t)NN * D1];      // layer1 output (elu, tf32-rounded)
__device__ float g_t2[(size_t)NN * D2];      // layer2 GEMM out
__device__ float g_as1[NN * H1];
__device__ float g_ad1[NN * H1];
__device__ float g_as2[NN * H2];
__device__ float g_ad2[NN * H2];
__device__ float g_m1[NN * H1];
__device__ float g_inv1[NN * H1];
__device__ float g_m2[NN * H2];
__device__ float g_inv2[NN * H2];
__device__ int   g_deg[NN];
__device__ int   g_rowptr[NN + 1];
__device__ int   g_fill[NN];
__device__ int   g_csrc[ET];
__device__ float g_pooled[BB * OUT_DIM];
__device__ int   g_cnt[BB];

__device__ __forceinline__ float lrelu(float x) { return x > 0.f ? x : 0.2f * x; }
__device__ __forceinline__ float elu(float x) { return x > 0.f ? x : expm1f(x); }

__device__ __forceinline__ float tf32r(float f) {
    uint32_t o;
    asm("cvt.rna.tf32.f32 %0, %1;" : "=r"(o) : "f"(f));
    return __uint_as_float(o);
}

// ---------------- prep (GEMM branch): round x/W1/W2 + zero alpha/pool -------
__global__ void prep_kernel(const float* __restrict__ x,
                            const float* __restrict__ W1,
                            const float* __restrict__ W2)
{
    int i = blockIdx.x * blockDim.x + threadIdx.x;
    const int nx = NN * IN_DIM / 4;
    const int n1 = D1 * IN_DIM / 4;
    const int n2 = D2 * D1 / 4;
    if (i < nx) {
        float4 v = ((const float4*)x)[i];
        v.x = tf32r(v.x); v.y = tf32r(v.y); v.z = tf32r(v.z); v.w = tf32r(v.w);
        ((float4*)g_xr)[i] = v;
    }
    if (i < n1) {
        float4 v = ((const float4*)W1)[i];
        v.x = tf32r(v.x); v.y = tf32r(v.y); v.z = tf32r(v.z); v.w = tf32r(v.w);
        ((float4*)g_w1r)[i] = v;
    }
    if (i < n2) {
        float4 v = ((const float4*)W2)[i];
        v.x = tf32r(v.x); v.y = tf32r(v.y); v.z = tf32r(v.z); v.w = tf32r(v.w);
        ((float4*)g_w2r)[i] = v;
    }
    if (i < NN * H1) { g_as1[i] = 0.f; g_ad1[i] = 0.f; }
    if (i < NN * H2) { g_as2[i] = 0.f; g_ad2[i] = 0.f; }
    if (i < BB * OUT_DIM) g_pooled[i] = 0.f;
    if (i < BB) g_cnt[i] = 0;
}

// ---------------- CSR branch (second stream) --------------------------------
__global__ void zero_csr_kernel() {
    int i = blockIdx.x * blockDim.x + threadIdx.x;
    if (i < NN) { g_deg[i] = 0; g_fill[i] = 0; }
}

__global__ void hist_kernel(const int* __restrict__ ei) {
    int e = blockIdx.x * blockDim.x + threadIdx.x;
    if (e >= ET) return;
    int dst = (e < EE) ? ei[EE + e] : (e - EE);
    atomicAdd(&g_deg[dst], 1);
}

__global__ void scan_kernel() {
    __shared__ int warp_sums[32];
    __shared__ int carry_s;
    int t = threadIdx.x, lane = t & 31, w = t >> 5;
    if (t == 0) { carry_s = 0; g_rowptr[0] = 0; }
    __syncthreads();
    for (int base = 0; base < NN; base += 1024) {
        int i = base + t;
        int x = (i < NN) ? g_deg[i] : 0;
#pragma unroll
        for (int o = 1; o < 32; o <<= 1) {
            int y = __shfl_up_sync(0xffffffffu, x, o);
            if (lane >= o) x += y;
        }
        if (lane == 31) warp_sums[w] = x;
        __syncthreads();
        if (w == 0) {
            int s = warp_sums[lane];
#pragma unroll
            for (int o = 1; o < 32; o <<= 1) {
                int y = __shfl_up_sync(0xffffffffu, s, o);
                if (lane >= o) s += y;
            }
            warp_sums[lane] = s;
        }
        __syncthreads();
        int pre = (w > 0 ? warp_sums[w - 1] : 0) + carry_s;
        if (i < NN) g_rowptr[i + 1] = x + pre;
        __syncthreads();
        if (t == 0) carry_s += warp_sums[31];
        __syncthreads();
    }
}

__global__ void scatter_kernel(const int* __restrict__ ei) {
    int e = blockIdx.x * blockDim.x + threadIdx.x;
    if (e >= ET) return;
    int src, dst;
    if (e < EE) { src = ei[e]; dst = ei[EE + e]; }
    else        { src = dst = e - EE; }
    int pos = g_rowptr[dst] + atomicAdd(&g_fill[dst], 1);
    g_csrc[pos] = src;
}

// ---------------- TF32 tensor-core GEMM (cp.async + ldmatrix) ---------------
// A and B both pre-rounded to tf32. B fragments use merged ldmatrix.x4.
#define TBM 128
#define TBN 128
#define TBK 16
#define A_BYTES (TBM * 64)
#define B_BYTES (TBN * 64)
#define STAGE_BYTES (A_BYTES + B_BYTES)   // 16384
#define NSTAGE 4
#define SMEM_BYTES (NSTAGE * STAGE_BYTES) // 65536

__device__ __forceinline__ int sw_of(int r) { return (r ^ (r >> 2)) & 3; }

__global__ __launch_bounds__(256, 2) void sgemm_tf32(
    const float* __restrict__ A, const float* __restrict__ B,
    float* __restrict__ C, int M, int N, int K,
    const float* __restrict__ av_src, const float* __restrict__ av_dst,
    float* __restrict__ out_as, float* __restrict__ out_ad,
    int head_bits, int nheads)
{
    extern __shared__ uint32_t smem[];
    const uint32_t smem_base = (uint32_t)__cvta_generic_to_shared(smem);

    const int tid  = threadIdx.x;
    const int lane = tid & 31;
    const int wid  = tid >> 5;
    const int g    = lane >> 2;
    const int tig  = lane & 3;
    const int wm   = wid >> 2;
    const int wn   = wid & 3;
    const int bm   = blockIdx.y * TBM;
    const int bn   = blockIdx.x * TBN;

    // A ldmatrix lane roles (x4: 16 rows x 2 chunks)
    const int rlA = (lane & 7) + ((lane >> 3) & 1) * 8;
    const int caA = lane >> 4;

    uint32_t aoff[4]; int aswz[4];
#pragma unroll
    for (int mt = 0; mt < 4; mt++) {
        int r = wm * 64 + mt * 16 + rlA;
        aoff[mt] = (uint32_t)(r * 64);
        aswz[mt] = sw_of(r);
    }

    // B ldmatrix x4 lane roles: group q=lane>>3 -> (nt pair member, k chunk)
    const int q  = lane >> 3;       // 0..3
    const int cq = q & 1;           // chunk select within kstep
    uint32_t boff2[2]; int bswz2[2];
#pragma unroll
    for (int p = 0; p < 2; p++) {
        int ntp = 2 * p + (q >> 1);
        int r = wn * 32 + ntp * 8 + (lane & 7);
        boff2[p] = (uint32_t)(A_BYTES + r * 64);
        bswz2[p] = sw_of(r);
    }

    float acc[4][4][4];
#pragma unroll
    for (int mt = 0; mt < 4; mt++)
#pragma unroll
        for (int nt = 0; nt < 4; nt++)
#pragma unroll
            for (int i = 0; i < 4; i++) acc[mt][nt][i] = 0.f;

    const int KT = K / TBK;

    auto load_stage = [&](int s, int kt) {
        const uint32_t base = smem_base + s * STAGE_BYTES;
        const int k0 = kt * TBK;
        {
            int m = tid >> 2, kc = tid & 3;
            uint32_t dst = base + (uint32_t)(m * 64 + ((kc ^ sw_of(m)) << 4));
            const float* src = A + (size_t)(bm + m) * K + k0 + kc * 4;
            asm volatile("cp.async.cg.shared.global [%0], [%1], 16;" :: "r"(dst), "l"(src));
            int c2 = tid + 256;
            int m2 = c2 >> 2, kc2 = c2 & 3;
            uint32_t dst2 = base + (uint32_t)(m2 * 64 + ((kc2 ^ sw_of(m2)) << 4));
            const float* src2 = A + (size_t)(bm + m2) * K + k0 + kc2 * 4;
            asm volatile("cp.async.cg.shared.global [%0], [%1], 16;" :: "r"(dst2), "l"(src2));
        }
        {
            int n = tid >> 2, kc = tid & 3;
            uint32_t dst = base + A_BYTES + (uint32_t)(n * 64 + ((kc ^ sw_of(n)) << 4));
            const float* src = B + (size_t)(bn + n) * K + k0 + kc * 4;
            asm volatile("cp.async.cg.shared.global [%0], [%1], 16;" :: "r"(dst), "l"(src));
            int c2 = tid + 256;
            int n2 = c2 >> 2, kc2 = c2 & 3;
            uint32_t dst2 = base + A_BYTES + (uint32_t)(n2 * 64 + ((kc2 ^ sw_of(n2)) << 4));
            const float* src2 = B + (size_t)(bn + n2) * K + k0 + kc2 * 4;
            asm volatile("cp.async.cg.shared.global [%0], [%1], 16;" :: "r"(dst2), "l"(src2));
        }
    };

#pragma unroll
    for (int s = 0; s < NSTAGE - 1; s++) {
        load_stage(s, s);
        asm volatile("cp.async.commit_group;");
    }

    for (int kt = 0; kt < KT; kt++) {
        const int s = kt & (NSTAGE - 1);
        asm volatile("cp.async.wait_group %0;" :: "n"(NSTAGE - 2));
        __syncthreads();

        const uint32_t base = smem_base + s * STAGE_BYTES;

#pragma unroll
        for (int ks = 0; ks < 2; ks++) {
            const int j0 = ks * 2;
            uint32_t af[4][4];
#pragma unroll
            for (int mt = 0; mt < 4; mt++) {
                uint32_t addr = base + aoff[mt] + (uint32_t)((((j0 + caA) ^ aswz[mt])) << 4);
                asm volatile("ldmatrix.sync.aligned.m8n8.x4.shared.b16 {%0,%1,%2,%3}, [%4];"
                    : "=r"(af[mt][0]), "=r"(af[mt][1]), "=r"(af[mt][2]), "=r"(af[mt][3])
                    : "r"(addr));
            }
            uint32_t bf[4][2];
#pragma unroll
            for (int p = 0; p < 2; p++) {
                uint32_t addr = base + boff2[p] + (uint32_t)((((j0 + cq) ^ bswz2[p])) << 4);
                asm volatile("ldmatrix.sync.aligned.m8n8.x4.shared.b16 {%0,%1,%2,%3}, [%4];"
                    : "=r"(bf[2 * p][0]), "=r"(bf[2 * p][1]),
                      "=r"(bf[2 * p + 1][0]), "=r"(bf[2 * p + 1][1])
                    : "r"(addr));
            }
#pragma unroll
            for (int mt = 0; mt < 4; mt++)
#pragma unroll
                for (int nt = 0; nt < 4; nt++) {
                    asm volatile(
                        "mma.sync.aligned.m16n8k8.row.col.f32.tf32.tf32.f32 "
                        "{%0,%1,%2,%3}, {%4,%5,%6,%7}, {%8,%9}, {%0,%1,%2,%3};"
                        : "+f"(acc[mt][nt][0]), "+f"(acc[mt][nt][1]),
                          "+f"(acc[mt][nt][2]), "+f"(acc[mt][nt][3])
                        : "r"(af[mt][0]), "r"(af[mt][1]), "r"(af[mt][2]), "r"(af[mt][3]),
                          "r"(bf[nt][0]), "r"(bf[nt][1]));
                }
        }

        if (kt + NSTAGE - 1 < KT) load_stage((kt + NSTAGE - 1) & (NSTAGE - 1), kt + NSTAGE - 1);
        asm volatile("cp.async.commit_group;");
    }

    // epilogue: store C
#pragma unroll
    for (int mt = 0; mt < 4; mt++) {
        int r0 = bm + wm * 64 + mt * 16 + g;
#pragma unroll
        for (int nt = 0; nt < 4; nt++) {
            int cc = bn + wn * 32 + nt * 8 + tig * 2;
            *(float2*)(C + (size_t)r0 * N + cc) = make_float2(acc[mt][nt][0], acc[mt][nt][1]);
            *(float2*)(C + (size_t)(r0 + 8) * N + cc) = make_float2(acc[mt][nt][2], acc[mt][nt][3]);
        }
    }

    // fused alpha epilogue
    if (av_src) {
        const int head = bn >> head_bits;
        const int omask = (1 << head_bits) - 1;
        const int obase = head << head_bits;
        float asv[4][2], adv[4][2];
#pragma unroll
        for (int nt = 0; nt < 4; nt++) {
#pragma unroll
            for (int i = 0; i < 2; i++) {
                int c = bn + wn * 32 + nt * 8 + tig * 2 + i;
                int o = c & omask;
                asv[nt][i] = av_src[obase + o];
                adv[nt][i] = av_dst[obase + o];
            }
        }
#pragma unroll
        for (int mt = 0; mt < 4; mt++) {
            float s0 = 0.f, s1 = 0.f, d0 = 0.f, d1 = 0.f;
#pragma unroll
            for (int nt = 0; nt < 4; nt++) {
                s0 += acc[mt][nt][0] * asv[nt][0] + acc[mt][nt][1] * asv[nt][1];
                d0 += acc[mt][nt][0] * adv[nt][0] + acc[mt][nt][1] * adv[nt][1];
                s1 += acc[mt][nt][2] * asv[nt][0] + acc[mt][nt][3] * asv[nt][1];
                d1 += acc[mt][nt][2] * adv[nt][0] + acc[mt][nt][3] * adv[nt][1];
            }
#pragma unroll
            for (int o = 1; o < 4; o <<= 1) {
                s0 += __shfl_xor_sync(0xffffffffu, s0, o);
                s1 += __shfl_xor_sync(0xffffffffu, s1, o);
                d0 += __shfl_xor_sync(0xffffffffu, d0, o);
                d1 += __shfl_xor_sync(0xffffffffu, d1, o);
            }
            if (tig == 0) {
                int r0 = bm + wm * 64 + mt * 16 + g;
                atomicAdd(&out_as[r0 * nheads + head], s0);
                atomicAdd(&out_ad[r0 * nheads + head], d0);
                atomicAdd(&out_as[(r0 + 8) * nheads + head], s1);
                atomicAdd(&out_ad[(r0 + 8) * nheads + head], d1);
            }
        }
    }
}

// ---------------- softmax stats: warp per node, shfl-only -------------------
__global__ __launch_bounds__(256) void stats1_kernel() {
    int n = (blockIdx.x * 256 + threadIdx.x) >> 5;
    int lane = threadIdx.x & 31;
    if (n >= NN) return;
    int row = g_rowptr[n], deg = g_rowptr[n + 1] - row;
    float4 adv = *(const float4*)(g_ad1 + n * 4);
    float m0 = -1e30f, m1 = -1e30f, m2 = -1e30f, m3 = -1e30f;
    for (int j = lane; j < deg; j += 32) {
        int s = g_csrc[row + j];
        float4 a = *(const float4*)(g_as1 + s * 4);
        m0 = fmaxf(m0, lrelu(a.x + adv.x));
        m1 = fmaxf(m1, lrelu(a.y + adv.y));
        m2 = fmaxf(m2, lrelu(a.z + adv.z));
        m3 = fmaxf(m3, lrelu(a.w + adv.w));
    }
#pragma unroll
    for (int o = 16; o; o >>= 1) {
        m0 = fmaxf(m0, __shfl_xor_sync(0xffffffffu, m0, o));
        m1 = fmaxf(m1, __shfl_xor_sync(0xffffffffu, m1, o));
        m2 = fmaxf(m2, __shfl_xor_sync(0xffffffffu, m2, o));
        m3 = fmaxf(m3, __shfl_xor_sync(0xffffffffu, m3, o));
    }
    float d0 = 0.f, d1 = 0.f, d2 = 0.f, d3 = 0.f;
    for (int j = lane; j < deg; j += 32) {
        int s = g_csrc[row + j];
        float4 a = *(const float4*)(g_as1 + s * 4);
        d0 += __expf(lrelu(a.x + adv.x) - m0);
        d1 += __expf(lrelu(a.y + adv.y) - m1);
        d2 += __expf(lrelu(a.z + adv.z) - m2);
        d3 += __expf(lrelu(a.w + adv.w) - m3);
    }
#pragma unroll
    for (int o = 16; o; o >>= 1) {
        d0 += __shfl_xor_sync(0xffffffffu, d0, o);
        d1 += __shfl_xor_sync(0xffffffffu, d1, o);
        d2 += __shfl_xor_sync(0xffffffffu, d2, o);
        d3 += __shfl_xor_sync(0xffffffffu, d3, o);
    }
    if (lane == 0) {
        *(float4*)(g_m1 + n * 4) = make_float4(m0, m1, m2, m3);
        *(float4*)(g_inv1 + n * 4) = make_float4(
            1.f / (d0 + 1e-16f), 1.f / (d1 + 1e-16f),
            1.f / (d2 + 1e-16f), 1.f / (d3 + 1e-16f));
    }
}

__global__ __launch_bounds__(256) void stats2_kernel() {
    int n = (blockIdx.x * 256 + threadIdx.x) >> 5;
    int lane = threadIdx.x & 31;
    if (n >= NN) return;
    int row = g_rowptr[n], deg = g_rowptr[n + 1] - row;
    float2 adv = *(const float2*)(g_ad2 + n * 2);
    float m0 = -1e30f, m1 = -1e30f;
    for (int j = lane; j < deg; j += 32) {
        int s = g_csrc[row + j];
        float2 a = *(const float2*)(g_as2 + s * 2);
        m0 = fmaxf(m0, lrelu(a.x + adv.x));
        m1 = fmaxf(m1, lrelu(a.y + adv.y));
    }
#pragma unroll
    for (int o = 16; o; o >>= 1) {
        m0 = fmaxf(m0, __shfl_xor_sync(0xffffffffu, m0, o));
        m1 = fmaxf(m1, __shfl_xor_sync(0xffffffffu, m1, o));
    }
    float d0 = 0.f, d1 = 0.f;
    for (int j = lane; j < deg; j += 32) {
        int s = g_csrc[row + j];
        float2 a = *(const float2*)(g_as2 + s * 2);
        d0 += __expf(lrelu(a.x + adv.x) - m0);
        d1 += __expf(lrelu(a.y + adv.y) - m1);
    }
#pragma unroll
    for (int o = 16; o; o >>= 1) {
        d0 += __shfl_xor_sync(0xffffffffu, d0, o);
        d1 += __shfl_xor_sync(0xffffffffu, d1, o);
    }
    if (lane == 0) {
        *(float2*)(g_m2 + n * 2) = make_float2(m0, m1);
        *(float2*)(g_inv2 + n * 2) = make_float2(1.f / (d0 + 1e-16f), 1.f / (d1 + 1e-16f));
    }
}

// ---------------- layer1 aggregation (block per node, no reductions) --------
#define CH1 512
__global__ __launch_bounds__(256) void gat1_agg(
    const float* __restrict__ h, const float* __restrict__ b1,
    float* __restrict__ out)
{
    __shared__ float s_ex[CH1 * 4];
    __shared__ int   s_src[CH1];
    int n = blockIdx.x, tid = threadIdx.x;
    int row = g_rowptr[n];
    int deg = g_rowptr[n + 1] - row;
    float4 adv = *(const float4*)(g_ad1 + n * 4);
    float4 m   = *(const float4*)(g_m1 + n * 4);
    float4 inv = *(const float4*)(g_inv1 + n * 4);

    const int head = tid >> 6;          // 0..3
    const int off  = (tid & 63) << 2;   // 0..252

    float4 acc = make_float4(0.f, 0.f, 0.f, 0.f);
    const float* hb = h + head * 256 + off;
    for (int base = 0; base < deg; base += CH1) {
        int cnt = min(CH1, deg - base);
        for (int j = tid; j < cnt; j += 256) {
            int s = g_csrc[row + base + j];
            s_src[j] = s;
            float4 a = *(const float4*)(g_as1 + s * 4);
            s_ex[j * 4 + 0] = __expf(lrelu(a.x + adv.x) - m.x) * inv.x;
            s_ex[j * 4 + 1] = __expf(lrelu(a.y + adv.y) - m.y) * inv.y;
            s_ex[j * 4 + 2] = __expf(lrelu(a.z + adv.z) - m.z) * inv.z;
            s_ex[j * 4 + 3] = __expf(lrelu(a.w + adv.w) - m.w) * inv.w;
        }
        __syncthreads();
#pragma unroll 4
        for (int j = 0; j < cnt; j++) {
            int s = s_src[j];
            float w = s_ex[j * 4 + head];
            float4 v = *(const float4*)(hb + (size_t)s * D1);
            acc.x = fmaf(v.x, w, acc.x);
            acc.y = fmaf(v.y, w, acc.y);
            acc.z = fmaf(v.z, w, acc.z);
            acc.w = fmaf(v.w, w, acc.w);
        }
        __syncthreads();
    }

    float4 bv = *(const float4*)(b1 + head * 256 + off);
    float4 o4;
    o4.x = tf32r(elu(acc.x + bv.x));
    o4.y = tf32r(elu(acc.y + bv.y));
    o4.z = tf32r(elu(acc.z + bv.z));
    o4.w = tf32r(elu(acc.w + bv.w));
    *(float4*)(out + (size_t)n * D1 + head * 256 + off) = o4;
}

// ---------------- layer2 aggregation (block per node, no reductions) --------
#define CH2 512
__global__ __launch_bounds__(128) void gat2_agg(
    const float* __restrict__ h, const float* __restrict__ b2,
    float* __restrict__ h2out)
{
    __shared__ float s_ex[CH2 * 2];
    __shared__ int   s_src[CH2];
    __shared__ float s_comb[128];
    int n = blockIdx.x, tid = threadIdx.x;
    int row = g_rowptr[n];
    int deg = g_rowptr[n + 1] - row;
    float2 adv = *(const float2*)(g_ad2 + n * 2);
    float2 m   = *(const float2*)(g_m2 + n * 2);
    float2 inv = *(const float2*)(g_inv2 + n * 2);

    const int head = tid >> 6;          // 0..1
    const int foff = (tid & 63) << 1;   // 0..126

    float2 acc = make_float2(0.f, 0.f);
    const float* hb = h + head * OUT_DIM + foff;
    for (int base = 0; base < deg; base += CH2) {
        int cnt = min(CH2, deg - base);
        for (int j = tid; j < cnt; j += 128) {
            int s = g_csrc[row + base + j];
            s_src[j] = s;
            float2 a = *(const float2*)(g_as2 + s * 2);
            s_ex[j * 2 + 0] = __expf(lrelu(a.x + adv.x) - m.x) * inv.x;
            s_ex[j * 2 + 1] = __expf(lrelu(a.y + adv.y) - m.y) * inv.y;
        }
        __syncthreads();
#pragma unroll 4
        for (int j = 0; j < cnt; j++) {
            int s = s_src[j];
            float w = s_ex[j * 2 + head];
            float2 v = *(const float2*)(hb + (size_t)s * D2);
            acc.x = fmaf(v.x, w, acc.x);
            acc.y = fmaf(v.y, w, acc.y);
        }
        __syncthreads();
    }

    if (head == 1) { s_comb[foff] = acc.x; s_comb[foff + 1] = acc.y; }
    __syncthreads();
    if (head == 0) {
        float ox = (acc.x + s_comb[foff]) * 0.5f + b2[foff];
        float oy = (acc.y + s_comb[foff + 1]) * 0.5f + b2[foff + 1];
        *(float2*)(h2out + (size_t)n * OUT_DIM + foff) = make_float2(elu(ox), elu(oy));
    }
}

// ---------------- pooling (run-length on sorted batch, 125 blocks) ----------
__global__ __launch_bounds__(128) void pool_kernel(
    const float* __restrict__ h2, const int* __restrict__ batch)
{
    __shared__ int s_b[128];
    int blk = blockIdx.x, f = threadIdx.x;
    int n0 = blk * 128;
    s_b[f] = batch[n0 + f];
    __syncthreads();

    float acc = 0.f;
    int cur = s_b[0];
    int cnt = 0;
#pragma unroll 4
    for (int j = 0; j < 128; j++) {
        int b = s_b[j];
        if (b != cur) {
            atomicAdd(&g_pooled[cur * OUT_DIM + f], acc);
            if (f == 0) atomicAdd(&g_cnt[cur], cnt);
            acc = 0.f; cnt = 0; cur = b;
        }
        acc += h2[(size_t)(n0 + j) * OUT_DIM + f];
        cnt++;
    }
    atomicAdd(&g_pooled[cur * OUT_DIM + f], acc);
    if (f == 0) atomicAdd(&g_cnt[cur], cnt);
}

// ---------------- proj + layernorm (block per graph, 768 threads) -----------
__global__ __launch_bounds__(768) void proj_ln_kernel(
    const float* __restrict__ W, const float* __restrict__ pb,
    const float* __restrict__ g, const float* __restrict__ beta,
    float* __restrict__ out)
{
    __shared__ float sp[OUT_DIM];
    __shared__ float red[768];
    int b = blockIdx.x, j = threadIdx.x;
    float c = (float)max(g_cnt[b], 1);
    if (j < OUT_DIM) sp[j] = g_pooled[b * OUT_DIM + j] / c;
    __syncthreads();
    float z = pb[j];
    const float* w = W + (size_t)j * OUT_DIM;
#pragma unroll 8
    for (int k = 0; k < OUT_DIM; k++) z = fmaf(sp[k], w[k], z);

    red[j] = z; __syncthreads();
    if (j < 256) red[j] += red[j + 512];
    __syncthreads();
    if (j < 256) red[j] += red[j + 256];
    __syncthreads();
    for (int off = 128; off; off >>= 1) { if (j < off) red[j] += red[j + off]; __syncthreads(); }
    float mean = red[0] / 768.f;
    __syncthreads();
    float dz = z - mean;
    red[j] = dz * dz; __syncthreads();
    if (j < 256) red[j] += red[j + 512];
    __syncthreads();
    if (j < 256) red[j] += red[j + 256];
    __syncthreads();
    for (int off = 128; off; off >>= 1) { if (j < off) red[j] += red[j + off]; __syncthreads(); }
    float var = red[0] / 768.f;
    out[(size_t)b * 768 + j] = dz * rsqrtf(var + LN_EPS) * g[j] + beta[j];
}

// ---------------- launch ----------------------------------------------------
extern "C" void kernel_launch(void* const* d_in, const int* in_sizes, int n_in,
                              void* d_out, int out_size)
{
    const float* x   = (const float*)d_in[0];
    const int*   ei  = (const int*)  d_in[1];
    const int*   bat = (const int*)  d_in[2];
    const float* W1  = (const float*)d_in[3];
    const float* a1s = (const float*)d_in[4];
    const float* a1d = (const float*)d_in[5];
    const float* b1  = (const float*)d_in[6];
    const float* W2  = (const float*)d_in[7];
    const float* a2s = (const float*)d_in[8];
    const float* a2d = (const float*)d_in[9];
    const float* b2  = (const float*)d_in[10];
    const float* pW  = (const float*)d_in[11];
    const float* pb  = (const float*)d_in[12];
    const float* lg  = (const float*)d_in[13];
    const float* lb  = (const float*)d_in[14];

    float* out = (float*)d_out;
    float* ge  = out;                 // (32, 768)
    float* h2  = out + BB * 768;      // (16000, 128)

    float *xr, *w1r, *w2r, *h1pre, *h1, *t2, *as1, *ad1, *as2, *ad2;
    cudaGetSymbolAddress((void**)&xr, g_xr);
    cudaGetSymbolAddress((void**)&w1r, g_w1r);
    cudaGetSymbolAddress((void**)&w2r, g_w2r);
    cudaGetSymbolAddress((void**)&h1pre, g_h1pre);
    cudaGetSymbolAddress((void**)&h1, g_h1);
    cudaGetSymbolAddress((void**)&t2, g_t2);
    cudaGetSymbolAddress((void**)&as1, g_as1);
    cudaGetSymbolAddress((void**)&ad1, g_ad1);
    cudaGetSymbolAddress((void**)&as2, g_as2);
    cudaGetSymbolAddress((void**)&ad2, g_ad2);

    cudaFuncSetAttribute(sgemm_tf32, cudaFuncAttributeMaxDynamicSharedMemorySize,
                         SMEM_BYTES);

    // fork a second stream for the CSR build (independent of prep/GEMM1)
    cudaStream_t s2;
    cudaStreamCreateWithFlags(&s2, cudaStreamNonBlocking);
    cudaEvent_t ev_fork, ev_join;
    cudaEventCreateWithFlags(&ev_fork, cudaEventDisableTiming);
    cudaEventCreateWithFlags(&ev_join, cudaEventDisableTiming);

    cudaEventRecord(ev_fork, 0);
    cudaStreamWaitEvent(s2, ev_fork, 0);

    // slots: 1 prep, 2 zero_csr, 3 hist, 4 GEMM1 (ncu capture slot)
    prep_kernel<<<(NN * IN_DIM / 4 + 255) / 256, 256>>>(x, W1, W2);          // 1 (s0)
    zero_csr_kernel<<<(NN + 255) / 256, 256, 0, s2>>>();                     // 2 (s2)
    hist_kernel<<<(ET + 255) / 256, 256, 0, s2>>>(ei);                       // 3 (s2)
    {
        dim3 grid(D1 / TBN, NN / TBM);   // (8, 125)                         // 4 (s0)
        sgemm_tf32<<<grid, 256, SMEM_BYTES>>>(xr, w1r, h1pre, NN, D1, IN_DIM,
                                              a1s, a1d, as1, ad1, 8, H1);
    }
    scan_kernel<<<1, 1024, 0, s2>>>();                                       // 5 (s2)
    scatter_kernel<<<(ET + 255) / 256, 256, 0, s2>>>(ei);                    // 6 (s2)
    cudaEventRecord(ev_join, s2);
    cudaStreamWaitEvent(0, ev_join, 0);

    stats1_kernel<<<(NN * 32 + 255) / 256, 256>>>();                         // 7
    gat1_agg<<<NN, 256>>>(h1pre, b1, h1);                                    // 8
    {
        dim3 grid(D2 / TBN, NN / TBM);   // (2, 125)                         // 9
        sgemm_tf32<<<grid, 256, SMEM_BYTES>>>(h1, w2r, t2, NN, D2, D1,
                                              a2s, a2d, as2, ad2, 7, H2);
    }
    stats2_kernel<<<(NN * 32 + 255) / 256, 256>>>();                         // 10
    gat2_agg<<<NN, 128>>>(t2, b2, h2);                                       // 11
    pool_kernel<<<NN / 128, 128>>>(h2, bat);                                 // 12
    proj_ln_kernel<<<BB, 768>>>(pW, pb, lg, lb, ge);                         // 13

    cudaEventDestroy(ev_fork);
    cudaEventDestroy(ev_join);
    cudaStreamDestroy(s2);
}

// round 17
// speedup vs baseline: 1.0789x; 1.0743x over previous
#include <cuda_runtime.h>
#include <cuda_fp16.h>
#include <cstdint>

#define NN 16000
#define EE 256000
#define ET 272000   // EE + NN self loops
#define BB 32
#define IN_DIM 768
#define HID 256
#define H1 4
#define OUT_DIM 128
#define H2 2
#define D1 (H1*HID)    // 1024
#define D2 (H2*OUT_DIM) // 256
#define LN_EPS 1e-5f

// ---------------- scratch (static device globals; no allocation allowed) ----
__device__ float  g_xr[(size_t)NN * IN_DIM]; // tf32-rounded x
__device__ float  g_w1r[D1 * IN_DIM];        // tf32-rounded W1
__device__ float  g_w2r[D2 * D1];            // tf32-rounded W2
__device__ __half g_h1pre[(size_t)NN * D1];  // layer1 GEMM out (fp16)
__device__ float  g_h1[(size_t)NN * D1];     // layer1 output (elu, tf32-rounded)
__device__ __half g_t2[(size_t)NN * D2];     // layer2 GEMM out (fp16)
__device__ float g_as1[NN * H1];
__device__ float g_ad1[NN * H1];
__device__ float g_as2[NN * H2];
__device__ float g_ad2[NN * H2];
__device__ float g_m1[NN * H1];
__device__ float g_inv1[NN * H1];
__device__ float g_m2[NN * H2];
__device__ float g_inv2[NN * H2];
__device__ int   g_deg[NN];
__device__ int   g_rowptr[NN + 1];
__device__ int   g_fill[NN];
__device__ int   g_csrc[ET];
__device__ float g_pooled[BB * OUT_DIM];
__device__ int   g_cnt[BB];

__device__ __forceinline__ float lrelu(float x) { return x > 0.f ? x : 0.2f * x; }
__device__ __forceinline__ float elu(float x) { return x > 0.f ? x : expm1f(x); }

__device__ __forceinline__ float tf32r(float f) {
    uint32_t o;
    asm("cvt.rna.tf32.f32 %0, %1;" : "=r"(o) : "f"(f));
    return __uint_as_float(o);
}

// ---------------- prep: round x/W1/W2 + zero alpha/pool ---------------------
__global__ void prep_kernel(const float* __restrict__ x,
                            const float* __restrict__ W1,
                            const float* __restrict__ W2)
{
    int i = blockIdx.x * blockDim.x + threadIdx.x;
    const int nx = NN * IN_DIM / 4;
    const int n1 = D1 * IN_DIM / 4;
    const int n2 = D2 * D1 / 4;
    if (i < nx) {
        float4 v = ((const float4*)x)[i];
        v.x = tf32r(v.x); v.y = tf32r(v.y); v.z = tf32r(v.z); v.w = tf32r(v.w);
        ((float4*)g_xr)[i] = v;
    }
    if (i < n1) {
        float4 v = ((const float4*)W1)[i];
        v.x = tf32r(v.x); v.y = tf32r(v.y); v.z = tf32r(v.z); v.w = tf32r(v.w);
        ((float4*)g_w1r)[i] = v;
    }
    if (i < n2) {
        float4 v = ((const float4*)W2)[i];
        v.x = tf32r(v.x); v.y = tf32r(v.y); v.z = tf32r(v.z); v.w = tf32r(v.w);
        ((float4*)g_w2r)[i] = v;
    }
    if (i < NN * H1) { g_as1[i] = 0.f; g_ad1[i] = 0.f; }
    if (i < NN * H2) { g_as2[i] = 0.f; g_ad2[i] = 0.f; }
    if (i < BB * OUT_DIM) g_pooled[i] = 0.f;
    if (i < BB) g_cnt[i] = 0;
}

// ---------------- CSR branch (second stream) --------------------------------
__global__ void zero_csr_kernel() {
    int i = blockIdx.x * blockDim.x + threadIdx.x;
    if (i < NN) { g_deg[i] = 0; g_fill[i] = 0; }
}

__global__ void hist_kernel(const int* __restrict__ ei) {
    int e = blockIdx.x * blockDim.x + threadIdx.x;
    if (e >= ET) return;
    int dst = (e < EE) ? ei[EE + e] : (e - EE);
    atomicAdd(&g_deg[dst], 1);
}

__global__ void scan_kernel() {
    __shared__ int warp_sums[32];
    __shared__ int carry_s;
    int t = threadIdx.x, lane = t & 31, w = t >> 5;
    if (t == 0) { carry_s = 0; g_rowptr[0] = 0; }
    __syncthreads();
    for (int base = 0; base < NN; base += 1024) {
        int i = base + t;
        int x = (i < NN) ? g_deg[i] : 0;
#pragma unroll
        for (int o = 1; o < 32; o <<= 1) {
            int y = __shfl_up_sync(0xffffffffu, x, o);
            if (lane >= o) x += y;
        }
        if (lane == 31) warp_sums[w] = x;
        __syncthreads();
        if (w == 0) {
            int s = warp_sums[lane];
#pragma unroll
            for (int o = 1; o < 32; o <<= 1) {
                int y = __shfl_up_sync(0xffffffffu, s, o);
                if (lane >= o) s += y;
            }
            warp_sums[lane] = s;
        }
        __syncthreads();
        int pre = (w > 0 ? warp_sums[w - 1] : 0) + carry_s;
        if (i < NN) g_rowptr[i + 1] = x + pre;
        __syncthreads();
        if (t == 0) carry_s += warp_sums[31];
        __syncthreads();
    }
}

__global__ void scatter_kernel(const int* __restrict__ ei) {
    int e = blockIdx.x * blockDim.x + threadIdx.x;
    if (e >= ET) return;
    int src, dst;
    if (e < EE) { src = ei[e]; dst = ei[EE + e]; }
    else        { src = dst = e - EE; }
    int pos = g_rowptr[dst] + atomicAdd(&g_fill[dst], 1);
    g_csrc[pos] = src;
}

// ---------------- TF32 mma.sync GEMM (cp.async + ldmatrix), half C out ------
// C[M,N] = A[M,K]*B[N,K]^T ; A,B fp32 pre-rounded to tf32. C stored as fp16.
// Fused alpha epilogue accumulates per-(row,head) dot products (fp32 atomics).
#define TBM 128
#define TBN 128
#define TBK 16
#define A_BYTES (TBM * 64)
#define B_BYTES (TBN * 64)
#define STAGE_BYTES (A_BYTES + B_BYTES)   // 16384
#define NSTAGE 4
#define SMEM_BYTES (NSTAGE * STAGE_BYTES) // 65536

__device__ __forceinline__ int sw_of(int r) { return (r ^ (r >> 2)) & 3; }

__global__ __launch_bounds__(256, 2) void sgemm_tf32(
    const float* __restrict__ A, const float* __restrict__ B,
    __half* __restrict__ C, int M, int N, int K,
    const float* __restrict__ av_src, const float* __restrict__ av_dst,
    float* __restrict__ out_as, float* __restrict__ out_ad,
    int head_bits, int nheads)
{
    extern __shared__ uint32_t smem_u32[];
    uint32_t* smem = smem_u32;
    const uint32_t smem_base = (uint32_t)__cvta_generic_to_shared(smem);

    const int tid  = threadIdx.x;
    const int lane = tid & 31;
    const int wid  = tid >> 5;
    const int g    = lane >> 2;
    const int tig  = lane & 3;
    const int wm   = wid >> 2;
    const int wn   = wid & 3;
    const int bm   = blockIdx.y * TBM;
    const int bn   = blockIdx.x * TBN;

    const int rlA = (lane & 7) + ((lane >> 3) & 1) * 8;
    const int caA = lane >> 4;
    const int rlB = lane & 7;
    const int cbB = (lane >> 3) & 1;

    uint32_t aoff[4]; int aswz[4];
#pragma unroll
    for (int mt = 0; mt < 4; mt++) {
        int r = wm * 64 + mt * 16 + rlA;
        aoff[mt] = (uint32_t)(r * 64);
        aswz[mt] = sw_of(r);
    }
    uint32_t boff[4]; int bswz[4];
#pragma unroll
    for (int nt = 0; nt < 4; nt++) {
        int r = wn * 32 + nt * 8 + rlB;
        boff[nt] = (uint32_t)(A_BYTES + r * 64);
        bswz[nt] = sw_of(r);
    }

    float acc[4][4][4];
#pragma unroll
    for (int mt = 0; mt < 4; mt++)
#pragma unroll
        for (int nt = 0; nt < 4; nt++)
#pragma unroll
            for (int i = 0; i < 4; i++) acc[mt][nt][i] = 0.f;

    const int KT = K / TBK;

    auto load_stage = [&](int s, int kt) {
        const uint32_t base = smem_base + s * STAGE_BYTES;
        const int k0 = kt * TBK;
        {
            int m = tid >> 2, kc = tid & 3;
            uint32_t dst = base + (uint32_t)(m * 64 + ((kc ^ sw_of(m)) << 4));
            const float* src = A + (size_t)(bm + m) * K + k0 + kc * 4;
            asm volatile("cp.async.cg.shared.global [%0], [%1], 16;" :: "r"(dst), "l"(src));
            int c2 = tid + 256;
            int m2 = c2 >> 2, kc2 = c2 & 3;
            uint32_t dst2 = base + (uint32_t)(m2 * 64 + ((kc2 ^ sw_of(m2)) << 4));
            const float* src2 = A + (size_t)(bm + m2) * K + k0 + kc2 * 4;
            asm volatile("cp.async.cg.shared.global [%0], [%1], 16;" :: "r"(dst2), "l"(src2));
        }
        {
            int n = tid >> 2, kc = tid & 3;
            uint32_t dst = base + A_BYTES + (uint32_t)(n * 64 + ((kc ^ sw_of(n)) << 4));
            const float* src = B + (size_t)(bn + n) * K + k0 + kc * 4;
            asm volatile("cp.async.cg.shared.global [%0], [%1], 16;" :: "r"(dst), "l"(src));
            int c2 = tid + 256;
            int n2 = c2 >> 2, kc2 = c2 & 3;
            uint32_t dst2 = base + A_BYTES + (uint32_t)(n2 * 64 + ((kc2 ^ sw_of(n2)) << 4));
            const float* src2 = B + (size_t)(bn + n2) * K + k0 + kc2 * 4;
            asm volatile("cp.async.cg.shared.global [%0], [%1], 16;" :: "r"(dst2), "l"(src2));
        }
    };

#pragma unroll
    for (int s = 0; s < NSTAGE - 1; s++) {
        load_stage(s, s);
        asm volatile("cp.async.commit_group;");
    }

    for (int kt = 0; kt < KT; kt++) {
        const int s = kt & (NSTAGE - 1);
        asm volatile("cp.async.wait_group %0;" :: "n"(NSTAGE - 2));
        __syncthreads();

        const uint32_t base = smem_base + s * STAGE_BYTES;

#pragma unroll
        for (int ks = 0; ks < 2; ks++) {
            const int j0 = ks * 2;
            uint32_t af[4][4];
#pragma unroll
            for (int mt = 0; mt < 4; mt++) {
                uint32_t addr = base + aoff[mt] + (uint32_t)((((j0 + caA) ^ aswz[mt])) << 4);
                asm volatile("ldmatrix.sync.aligned.m8n8.x4.shared.b16 {%0,%1,%2,%3}, [%4];"
                    : "=r"(af[mt][0]), "=r"(af[mt][1]), "=r"(af[mt][2]), "=r"(af[mt][3])
                    : "r"(addr));
            }
            uint32_t bf[4][2];
#pragma unroll
            for (int nt = 0; nt < 4; nt++) {
                uint32_t addr = base + boff[nt] + (uint32_t)((((j0 + cbB) ^ bswz[nt])) << 4);
                asm volatile("ldmatrix.sync.aligned.m8n8.x2.shared.b16 {%0,%1}, [%2];"
                    : "=r"(bf[nt][0]), "=r"(bf[nt][1])
                    : "r"(addr));
            }
#pragma unroll
            for (int mt = 0; mt < 4; mt++)
#pragma unroll
                for (int nt = 0; nt < 4; nt++) {
                    asm volatile(
                        "mma.sync.aligned.m16n8k8.row.col.f32.tf32.tf32.f32 "
                        "{%0,%1,%2,%3}, {%4,%5,%6,%7}, {%8,%9}, {%0,%1,%2,%3};"
                        : "+f"(acc[mt][nt][0]), "+f"(acc[mt][nt][1]),
                          "+f"(acc[mt][nt][2]), "+f"(acc[mt][nt][3])
                        : "r"(af[mt][0]), "r"(af[mt][1]), "r"(af[mt][2]), "r"(af[mt][3]),
                          "r"(bf[nt][0]), "r"(bf[nt][1]));
                }
        }

        if (kt + NSTAGE - 1 < KT) load_stage((kt + NSTAGE - 1) & (NSTAGE - 1), kt + NSTAGE - 1);
        asm volatile("cp.async.commit_group;");
    }

    // epilogue: store C as fp16 (rn)
#pragma unroll
    for (int mt = 0; mt < 4; mt++) {
        int r0 = bm + wm * 64 + mt * 16 + g;
#pragma unroll
        for (int nt = 0; nt < 4; nt++) {
            int cc = bn + wn * 32 + nt * 8 + tig * 2;
            __half2 v0 = __floats2half2_rn(acc[mt][nt][0], acc[mt][nt][1]);
            __half2 v1 = __floats2half2_rn(acc[mt][nt][2], acc[mt][nt][3]);
            *(__half2*)(C + (size_t)r0 * N + cc) = v0;
            *(__half2*)(C + (size_t)(r0 + 8) * N + cc) = v1;
        }
    }

    // fused alpha epilogue (fp32 accs)
    if (av_src) {
        const int head = bn >> head_bits;
        const int omask = (1 << head_bits) - 1;
        const int obase = head << head_bits;
        float asv[4][2], adv[4][2];
#pragma unroll
        for (int nt = 0; nt < 4; nt++) {
#pragma unroll
            for (int i = 0; i < 2; i++) {
                int c = bn + wn * 32 + nt * 8 + tig * 2 + i;
                int o = c & omask;
                asv[nt][i] = av_src[obase + o];
                adv[nt][i] = av_dst[obase + o];
            }
        }
#pragma unroll
        for (int mt = 0; mt < 4; mt++) {
            float s0 = 0.f, s1 = 0.f, d0 = 0.f, d1 = 0.f;
#pragma unroll
            for (int nt = 0; nt < 4; nt++) {
                s0 += acc[mt][nt][0] * asv[nt][0] + acc[mt][nt][1] * asv[nt][1];
                d0 += acc[mt][nt][0] * adv[nt][0] + acc[mt][nt][1] * adv[nt][1];
                s1 += acc[mt][nt][2] * asv[nt][0] + acc[mt][nt][3] * asv[nt][1];
                d1 += acc[mt][nt][2] * adv[nt][0] + acc[mt][nt][3] * adv[nt][1];
            }
#pragma unroll
            for (int o = 1; o < 4; o <<= 1) {
                s0 += __shfl_xor_sync(0xffffffffu, s0, o);
                s1 += __shfl_xor_sync(0xffffffffu, s1, o);
                d0 += __shfl_xor_sync(0xffffffffu, d0, o);
                d1 += __shfl_xor_sync(0xffffffffu, d1, o);
            }
            if (tig == 0) {
                int r0 = bm + wm * 64 + mt * 16 + g;
                atomicAdd(&out_as[r0 * nheads + head], s0);
                atomicAdd(&out_ad[r0 * nheads + head], d0);
                atomicAdd(&out_as[(r0 + 8) * nheads + head], s1);
                atomicAdd(&out_ad[(r0 + 8) * nheads + head], d1);
            }
        }
    }
}

// ---------------- softmax stats: warp per node, shfl-only -------------------
__global__ __launch_bounds__(256) void stats1_kernel() {
    int n = (blockIdx.x * 256 + threadIdx.x) >> 5;
    int lane = threadIdx.x & 31;
    if (n >= NN) return;
    int row = g_rowptr[n], deg = g_rowptr[n + 1] - row;
    float4 adv = *(const float4*)(g_ad1 + n * 4);
    float m0 = -1e30f, m1 = -1e30f, m2 = -1e30f, m3 = -1e30f;
    for (int j = lane; j < deg; j += 32) {
        int s = g_csrc[row + j];
        float4 a = *(const float4*)(g_as1 + s * 4);
        m0 = fmaxf(m0, lrelu(a.x + adv.x));
        m1 = fmaxf(m1, lrelu(a.y + adv.y));
        m2 = fmaxf(m2, lrelu(a.z + adv.z));
        m3 = fmaxf(m3, lrelu(a.w + adv.w));
    }
#pragma unroll
    for (int o = 16; o; o >>= 1) {
        m0 = fmaxf(m0, __shfl_xor_sync(0xffffffffu, m0, o));
        m1 = fmaxf(m1, __shfl_xor_sync(0xffffffffu, m1, o));
        m2 = fmaxf(m2, __shfl_xor_sync(0xffffffffu, m2, o));
        m3 = fmaxf(m3, __shfl_xor_sync(0xffffffffu, m3, o));
    }
    float d0 = 0.f, d1 = 0.f, d2 = 0.f, d3 = 0.f;
    for (int j = lane; j < deg; j += 32) {
        int s = g_csrc[row + j];
        float4 a = *(const float4*)(g_as1 + s * 4);
        d0 += __expf(lrelu(a.x + adv.x) - m0);
        d1 += __expf(lrelu(a.y + adv.y) - m1);
        d2 += __expf(lrelu(a.z + adv.z) - m2);
        d3 += __expf(lrelu(a.w + adv.w) - m3);
    }
#pragma unroll
    for (int o = 16; o; o >>= 1) {
        d0 += __shfl_xor_sync(0xffffffffu, d0, o);
        d1 += __shfl_xor_sync(0xffffffffu, d1, o);
        d2 += __shfl_xor_sync(0xffffffffu, d2, o);
        d3 += __shfl_xor_sync(0xffffffffu, d3, o);
    }
    if (lane == 0) {
        *(float4*)(g_m1 + n * 4) = make_float4(m0, m1, m2, m3);
        *(float4*)(g_inv1 + n * 4) = make_float4(
            1.f / (d0 + 1e-16f), 1.f / (d1 + 1e-16f),
            1.f / (d2 + 1e-16f), 1.f / (d3 + 1e-16f));
    }
}

__global__ __launch_bounds__(256) void stats2_kernel() {
    int n = (blockIdx.x * 256 + threadIdx.x) >> 5;
    int lane = threadIdx.x & 31;
    if (n >= NN) return;
    int row = g_rowptr[n], deg = g_rowptr[n + 1] - row;
    float2 adv = *(const float2*)(g_ad2 + n * 2);
    float m0 = -1e30f, m1 = -1e30f;
    for (int j = lane; j < deg; j += 32) {
        int s = g_csrc[row + j];
        float2 a = *(const float2*)(g_as2 + s * 2);
        m0 = fmaxf(m0, lrelu(a.x + adv.x));
        m1 = fmaxf(m1, lrelu(a.y + adv.y));
    }
#pragma unroll
    for (int o = 16; o; o >>= 1) {
        m0 = fmaxf(m0, __shfl_xor_sync(0xffffffffu, m0, o));
        m1 = fmaxf(m1, __shfl_xor_sync(0xffffffffu, m1, o));
    }
    float d0 = 0.f, d1 = 0.f;
    for (int j = lane; j < deg; j += 32) {
        int s = g_csrc[row + j];
        float2 a = *(const float2*)(g_as2 + s * 2);
        d0 += __expf(lrelu(a.x + adv.x) - m0);
        d1 += __expf(lrelu(a.y + adv.y) - m1);
    }
#pragma unroll
    for (int o = 16; o; o >>= 1) {
        d0 += __shfl_xor_sync(0xffffffffu, d0, o);
        d1 += __shfl_xor_sync(0xffffffffu, d1, o);
    }
    if (lane == 0) {
        *(float2*)(g_m2 + n * 2) = make_float2(m0, m1);
        *(float2*)(g_inv2 + n * 2) = make_float2(1.f / (d0 + 1e-16f), 1.f / (d1 + 1e-16f));
    }
}

// ---------------- layer1 aggregation (block per node, fp16 gather) ----------
#define CH1 512
__global__ __launch_bounds__(256) void gat1_agg(
    const __half* __restrict__ h, const float* __restrict__ b1,
    float* __restrict__ out)
{
    __shared__ float s_ex[CH1 * 4];
    __shared__ int   s_src[CH1];
    int n = blockIdx.x, tid = threadIdx.x;
    int row = g_rowptr[n];
    int deg = g_rowptr[n + 1] - row;
    float4 adv = *(const float4*)(g_ad1 + n * 4);
    float4 m   = *(const float4*)(g_m1 + n * 4);
    float4 inv = *(const float4*)(g_inv1 + n * 4);

    const int head = tid >> 6;          // 0..3
    const int off  = (tid & 63) << 2;   // 0..252

    float4 acc = make_float4(0.f, 0.f, 0.f, 0.f);
    const __half* hb = h + head * 256 + off;
    for (int base = 0; base < deg; base += CH1) {
        int cnt = min(CH1, deg - base);
        for (int j = tid; j < cnt; j += 256) {
            int s = g_csrc[row + base + j];
            s_src[j] = s;
            float4 a = *(const float4*)(g_as1 + s * 4);
            s_ex[j * 4 + 0] = __expf(lrelu(a.x + adv.x) - m.x) * inv.x;
            s_ex[j * 4 + 1] = __expf(lrelu(a.y + adv.y) - m.y) * inv.y;
            s_ex[j * 4 + 2] = __expf(lrelu(a.z + adv.z) - m.z) * inv.z;
            s_ex[j * 4 + 3] = __expf(lrelu(a.w + adv.w) - m.w) * inv.w;
        }
        __syncthreads();
#pragma unroll 4
        for (int j = 0; j < cnt; j++) {
            int s = s_src[j];
            float w = s_ex[j * 4 + head];
            uint2 u = *(const uint2*)(hb + (size_t)s * D1);
            float2 f01 = __half22float2(*(const __half2*)&u.x);
            float2 f23 = __half22float2(*(const __half2*)&u.y);
            acc.x = fmaf(f01.x, w, acc.x);
            acc.y = fmaf(f01.y, w, acc.y);
            acc.z = fmaf(f23.x, w, acc.z);
            acc.w = fmaf(f23.y, w, acc.w);
        }
        __syncthreads();
    }

    float4 bv = *(const float4*)(b1 + head * 256 + off);
    float4 o4;
    o4.x = tf32r(elu(acc.x + bv.x));
    o4.y = tf32r(elu(acc.y + bv.y));
    o4.z = tf32r(elu(acc.z + bv.z));
    o4.w = tf32r(elu(acc.w + bv.w));
    *(float4*)(out + (size_t)n * D1 + head * 256 + off) = o4;
}

// ---------------- layer2 aggregation (block per node, fp16 gather) ----------
#define CH2 512
__global__ __launch_bounds__(128) void gat2_agg(
    const __half* __restrict__ h, const float* __restrict__ b2,
    float* __restrict__ h2out)
{
    __shared__ float s_ex[CH2 * 2];
    __shared__ int   s_src[CH2];
    __shared__ float s_comb[128];
    int n = blockIdx.x, tid = threadIdx.x;
    int row = g_rowptr[n];
    int deg = g_rowptr[n + 1] - row;
    float2 adv = *(const float2*)(g_ad2 + n * 2);
    float2 m   = *(const float2*)(g_m2 + n * 2);
    float2 inv = *(const float2*)(g_inv2 + n * 2);

    const int head = tid >> 6;          // 0..1
    const int foff = (tid & 63) << 1;   // 0..126

    float2 acc = make_float2(0.f, 0.f);
    const __half* hb = h + head * OUT_DIM + foff;
    for (int base = 0; base < deg; base += CH2) {
        int cnt = min(CH2, deg - base);
        for (int j = tid; j < cnt; j += 128) {
            int s = g_csrc[row + base + j];
            s_src[j] = s;
            float2 a = *(const float2*)(g_as2 + s * 2);
            s_ex[j * 2 + 0] = __expf(lrelu(a.x + adv.x) - m.x) * inv.x;
            s_ex[j * 2 + 1] = __expf(lrelu(a.y + adv.y) - m.y) * inv.y;
        }
        __syncthreads();
#pragma unroll 4
        for (int j = 0; j < cnt; j++) {
            int s = s_src[j];
            float w = s_ex[j * 2 + head];
            float2 v = __half22float2(*(const __half2*)(hb + (size_t)s * D2));
            acc.x = fmaf(v.x, w, acc.x);
            acc.y = fmaf(v.y, w, acc.y);
        }
        __syncthreads();
    }

    if (head == 1) { s_comb[foff] = acc.x; s_comb[foff + 1] = acc.y; }
    __syncthreads();
    if (head == 0) {
        float ox = (acc.x + s_comb[foff]) * 0.5f + b2[foff];
        float oy = (acc.y + s_comb[foff + 1]) * 0.5f + b2[foff + 1];
        *(float2*)(h2out + (size_t)n * OUT_DIM + foff) = make_float2(elu(ox), elu(oy));
    }
}

// ---------------- pooling (run-length on sorted batch, 125 blocks) ----------
__global__ __launch_bounds__(128) void pool_kernel(
    const float* __restrict__ h2, const int* __restrict__ batch)
{
    __shared__ int s_b[128];
    int blk = blockIdx.x, f = threadIdx.x;
    int n0 = blk * 128;
    s_b[f] = batch[n0 + f];
    __syncthreads();

    float acc = 0.f;
    int cur = s_b[0];
    int cnt = 0;
#pragma unroll 4
    for (int j = 0; j < 128; j++) {
        int b = s_b[j];
        if (b != cur) {
            atomicAdd(&g_pooled[cur * OUT_DIM + f], acc);
            if (f == 0) atomicAdd(&g_cnt[cur], cnt);
            acc = 0.f; cnt = 0; cur = b;
        }
        acc += h2[(size_t)(n0 + j) * OUT_DIM + f];
        cnt++;
    }
    atomicAdd(&g_pooled[cur * OUT_DIM + f], acc);
    if (f == 0) atomicAdd(&g_cnt[cur], cnt);
}

// ---------------- proj + layernorm (block per graph, 768 threads) -----------
__global__ __launch_bounds__(768) void proj_ln_kernel(
    const float* __restrict__ W, const float* __restrict__ pb,
    const float* __restrict__ g, const float* __restrict__ beta,
    float* __restrict__ out)
{
    __shared__ float sp[OUT_DIM];
    __shared__ float red[768];
    int b = blockIdx.x, j = threadIdx.x;
    float c = (float)max(g_cnt[b], 1);
    if (j < OUT_DIM) sp[j] = g_pooled[b * OUT_DIM + j] / c;
    __syncthreads();
    float z = pb[j];
    const float* w = W + (size_t)j * OUT_DIM;
#pragma unroll 8
    for (int k = 0; k < OUT_DIM; k++) z = fmaf(sp[k], w[k], z);

    red[j] = z; __syncthreads();
    if (j < 256) red[j] += red[j + 512];
    __syncthreads();
    if (j < 256) red[j] += red[j + 256];
    __syncthreads();
    for (int off = 128; off; off >>= 1) { if (j < off) red[j] += red[j + off]; __syncthreads(); }
    float mean = red[0] / 768.f;
    __syncthreads();
    float dz = z - mean;
    red[j] = dz * dz; __syncthreads();
    if (j < 256) red[j] += red[j + 512];
    __syncthreads();
    if (j < 256) red[j] += red[j + 256];
    __syncthreads();
    for (int off = 128; off; off >>= 1) { if (j < off) red[j] += red[j + off]; __syncthreads(); }
    float var = red[0] / 768.f;
    out[(size_t)b * 768 + j] = dz * rsqrtf(var + LN_EPS) * g[j] + beta[j];
}

// ---------------- launch ----------------------------------------------------
extern "C" void kernel_launch(void* const* d_in, const int* in_sizes, int n_in,
                              void* d_out, int out_size)
{
    const float* x   = (const float*)d_in[0];
    const int*   ei  = (const int*)  d_in[1];
    const int*   bat = (const int*)  d_in[2];
    const float* W1  = (const float*)d_in[3];
    const float* a1s = (const float*)d_in[4];
    const float* a1d = (const float*)d_in[5];
    const float* b1  = (const float*)d_in[6];
    const float* W2  = (const float*)d_in[7];
    const float* a2s = (const float*)d_in[8];
    const float* a2d = (const float*)d_in[9];
    const float* b2  = (const float*)d_in[10];
    const float* pW  = (const float*)d_in[11];
    const float* pb  = (const float*)d_in[12];
    const float* lg  = (const float*)d_in[13];
    const float* lb  = (const float*)d_in[14];

    float* out = (float*)d_out;
    float* ge  = out;                 // (32, 768)
    float* h2  = out + BB * 768;      // (16000, 128)

    float *xr, *w1r, *w2r, *h1, *as1, *ad1, *as2, *ad2;
    __half *h1pre, *t2;
    cudaGetSymbolAddress((void**)&xr, g_xr);
    cudaGetSymbolAddress((void**)&w1r, g_w1r);
    cudaGetSymbolAddress((void**)&w2r, g_w2r);
    cudaGetSymbolAddress((void**)&h1pre, g_h1pre);
    cudaGetSymbolAddress((void**)&h1, g_h1);
    cudaGetSymbolAddress((void**)&t2, g_t2);
    cudaGetSymbolAddress((void**)&as1, g_as1);
    cudaGetSymbolAddress((void**)&ad1, g_ad1);
    cudaGetSymbolAddress((void**)&as2, g_as2);
    cudaGetSymbolAddress((void**)&ad2, g_ad2);

    cudaFuncSetAttribute(sgemm_tf32, cudaFuncAttributeMaxDynamicSharedMemorySize,
                         SMEM_BYTES);

    // fork a second stream for the CSR build (independent of prep/GEMM1)
    cudaStream_t s2;
    cudaStreamCreateWithFlags(&s2, cudaStreamNonBlocking);
    cudaEvent_t ev_fork, ev_join;
    cudaEventCreateWithFlags(&ev_fork, cudaEventDisableTiming);
    cudaEventCreateWithFlags(&ev_join, cudaEventDisableTiming);

    cudaEventRecord(ev_fork, 0);
    cudaStreamWaitEvent(s2, ev_fork, 0);

    // slots: 1 prep, 2 zero_csr, 3 hist, 4 GEMM1 (ncu capture slot)
    prep_kernel<<<(NN * IN_DIM / 4 + 255) / 256, 256>>>(x, W1, W2);          // 1 (s0)
    zero_csr_kernel<<<(NN + 255) / 256, 256, 0, s2>>>();                     // 2 (s2)
    hist_kernel<<<(ET + 255) / 256, 256, 0, s2>>>(ei);                       // 3 (s2)
    {
        dim3 grid(D1 / TBN, NN / TBM);   // (8, 125)                         // 4 (s0)
        sgemm_tf32<<<grid, 256, SMEM_BYTES>>>(xr, w1r, h1pre, NN, D1, IN_DIM,
                                              a1s, a1d, as1, ad1, 8, H1);
    }
    scan_kernel<<<1, 1024, 0, s2>>>();                                       // 5 (s2)
    scatter_kernel<<<(ET + 255) / 256, 256, 0, s2>>>(ei);                    // 6 (s2)
    cudaEventRecord(ev_join, s2);
    cudaStreamWaitEvent(0, ev_join, 0);

    stats1_kernel<<<(NN * 32 + 255) / 256, 256>>>();                         // 7
    gat1_agg<<<NN, 256>>>(h1pre, b1, h1);                                    // 8
    {
        dim3 grid(D2 / TBN, NN / TBM);   // (2, 125)                         // 9
        sgemm_tf32<<<grid, 256, SMEM_BYTES>>>(h1, w2r, t2, NN, D2, D1,
                                              a2s, a2d, as2, ad2, 7, H2);
    }
    stats2_kernel<<<(NN * 32 + 255) / 256, 256>>>();                         // 10
    gat2_agg<<<NN, 128>>>(t2, b2, h2);                                       // 11
    pool_kernel<<<NN / 128, 128>>>(h2, bat);                                 // 12
    proj_ln_kernel<<<BB, 768>>>(pW, pb, lg, lb, ge);                         // 13

    cudaEventDestroy(ev_fork);
    cudaEventDestroy(ev_join);
    cudaStreamDestroy(s2);
}